// round 12
// baseline (speedup 1.0000x reference)
#include <cuda_runtime.h>
#include <math.h>

#define IMG_H 800.0f
#define IMG_W 1280.0f
#define FSCALE (1.0f/16.0f)
#define PP 14
#define NUM_CLASSES 80
#define SCORE_TH 0.05f
#define NMS_TH 0.5f
#define MAX_DET 100
#define IOU_TH 0.5f
#define SCALE_CLAMP 4.135166556742356f
#define FH 50
#define FW 80
#define FC 1024
#define NIMG 2
#define NR 256
#define NGT 64
#define NPROP (NIMG * NR)          // 512
#define NCOL 96                    // padded output cols: 0..80 cls, 81..84 box
#define KSPLIT 8
#define KSLICE (FC / KSPLIT)       // 128
#define MTILE 32

// Scratch (device globals; no allocation allowed)
__device__ float g_featvec[NPROP * FC];
__device__ float g_boxes[NPROP * 4];
__device__ float g_scores[NPROP];
__device__ float g_part[KSPLIT * NPROP * NCOL];  // split-K partials
__device__ float g_sboxes[NPROP * 4];            // score-sorted boxes
__device__ int   g_rank[NPROP];                  // sorted position per proposal
__device__ unsigned int g_supmask[NPROP * 8];    // suppression bitmatrix

// ---------------------------------------------------------------------------
// Kernel 1: ROIAlign + fused weight-table build + fused GT matching.
// grid(256, 2) = (box, image), block(256). Thread t owns channels [4t,4t+4).
// Prologue: thread 0 builds the separable y-weight table into smem, thread 32
// the x-table, thread 64 does this box's GT match (all independent).
// Main loop: 8-wide x-unroll, 8 independent accumulator sets -> MLP 8.
// ---------------------------------------------------------------------------
__global__ void roi_kernel(const float* __restrict__ feat,
                           const float* __restrict__ prop,
                           const float* __restrict__ gt,
                           float* __restrict__ featvec,
                           float* __restrict__ out_idx,
                           float* __restrict__ out_lbl) {
    __shared__ float wyS[FH];
    __shared__ float wxS[FW];
    __shared__ int bndS[4];

    int box = blockIdx.x;
    int n = blockIdx.y;
    int gid = n * NR + box;
    int t = threadIdx.x;

    if (t < FH) wyS[t] = 0.0f;
    if (t >= 64 && t < 64 + FW) wxS[t - 64] = 0.0f;
    __syncthreads();

    const float* p = prop + (size_t)gid * 4;

    if (t == 0) {
        float y1 = p[1] * FSCALE, y2 = p[3] * FSCALE;
        float bh = (y2 - y1) * (1.0f / (float)PP);
        int lo = FH, hi = 0;
        for (int py = 0; py < PP; py++) {
            float gy = y1 + ((float)py + 0.5f) * bh - 0.5f;
            gy = fminf(fmaxf(gy, 0.0f), (float)(FH - 1));
            float y0 = floorf(gy);
            int y0i = (int)y0;
            int y1i = min(y0i + 1, FH - 1);
            float ly = gy - y0;
            wyS[y0i] += 1.0f - ly;
            wyS[y1i] += ly;
            lo = min(lo, y0i);
            hi = max(hi, y1i);
        }
        bndS[0] = lo; bndS[1] = hi;
    } else if (t == 32) {
        float x1 = p[0] * FSCALE, x2 = p[2] * FSCALE;
        float bw = (x2 - x1) * (1.0f / (float)PP);
        int lo = FW, hi = 0;
        for (int px = 0; px < PP; px++) {
            float gx = x1 + ((float)px + 0.5f) * bw - 0.5f;
            gx = fminf(fmaxf(gx, 0.0f), (float)(FW - 1));
            float x0 = floorf(gx);
            int x0i = (int)x0;
            int x1i = min(x0i + 1, FW - 1);
            float lx = gx - x0;
            wxS[x0i] += 1.0f - lx;
            wxS[x1i] += lx;
            lo = min(lo, x0i);
            hi = max(hi, x1i);
        }
        bndS[2] = lo; bndS[3] = hi;
    } else if (t == 64) {
        float px1 = p[0], py1 = p[1], px2 = p[2], py2 = p[3];
        float pa = (px2 - px1) * (py2 - py1);
        float best = -1.0f;
        int bi = 0;
        for (int g = 0; g < NGT; g++) {
            const float* gb = gt + (n * NGT + g) * 4;
            float gx1 = gb[0], gy1 = gb[1], gx2 = gb[2], gy2 = gb[3];
            float ga = (gx2 - gx1) * (gy2 - gy1);
            float lx = fmaxf(gx1, px1), ly = fmaxf(gy1, py1);
            float rx = fminf(gx2, px2), ry = fminf(gy2, py2);
            float w = fmaxf(rx - lx, 0.0f), h = fmaxf(ry - ly, 0.0f);
            float inter = w * h;
            float iou = inter / fmaxf(ga + pa - inter, 1e-9f);
            if (iou > best) { best = iou; bi = g; }
        }
        out_idx[gid] = (float)bi;
        out_lbl[gid] = (best >= IOU_TH) ? 1.0f : 0.0f;
    }
    __syncthreads();

    int ylo = bndS[0], yhi = bndS[1], xlo = bndS[2], xhi = bndS[3];

    const float4* f = (const float4*)(feat + (size_t)n * FH * FW * FC) + t;
    float4 a0 = make_float4(0.f, 0.f, 0.f, 0.f);
    float4 a1 = make_float4(0.f, 0.f, 0.f, 0.f);
    float4 a2 = make_float4(0.f, 0.f, 0.f, 0.f);
    float4 a3 = make_float4(0.f, 0.f, 0.f, 0.f);
    float4 a4 = make_float4(0.f, 0.f, 0.f, 0.f);
    float4 a5 = make_float4(0.f, 0.f, 0.f, 0.f);
    float4 a6 = make_float4(0.f, 0.f, 0.f, 0.f);
    float4 a7 = make_float4(0.f, 0.f, 0.f, 0.f);

    for (int y = ylo; y <= yhi; y++) {
        float wyv = wyS[y];
        const float4* rowp = f + (size_t)(y * FW) * (FC / 4);
        int x = xlo;
        for (; x + 7 <= xhi; x += 8) {
            float w0 = wyv * wxS[x];
            float w1 = wyv * wxS[x + 1];
            float w2 = wyv * wxS[x + 2];
            float w3 = wyv * wxS[x + 3];
            float w4 = wyv * wxS[x + 4];
            float w5 = wyv * wxS[x + 5];
            float w6 = wyv * wxS[x + 6];
            float w7 = wyv * wxS[x + 7];
            float4 v0 = rowp[(size_t)x * (FC / 4)];
            float4 v1 = rowp[(size_t)(x + 1) * (FC / 4)];
            float4 v2 = rowp[(size_t)(x + 2) * (FC / 4)];
            float4 v3 = rowp[(size_t)(x + 3) * (FC / 4)];
            float4 v4 = rowp[(size_t)(x + 4) * (FC / 4)];
            float4 v5 = rowp[(size_t)(x + 5) * (FC / 4)];
            float4 v6 = rowp[(size_t)(x + 6) * (FC / 4)];
            float4 v7 = rowp[(size_t)(x + 7) * (FC / 4)];
            a0.x += w0 * v0.x; a0.y += w0 * v0.y; a0.z += w0 * v0.z; a0.w += w0 * v0.w;
            a1.x += w1 * v1.x; a1.y += w1 * v1.y; a1.z += w1 * v1.z; a1.w += w1 * v1.w;
            a2.x += w2 * v2.x; a2.y += w2 * v2.y; a2.z += w2 * v2.z; a2.w += w2 * v2.w;
            a3.x += w3 * v3.x; a3.y += w3 * v3.y; a3.z += w3 * v3.z; a3.w += w3 * v3.w;
            a4.x += w4 * v4.x; a4.y += w4 * v4.y; a4.z += w4 * v4.z; a4.w += w4 * v4.w;
            a5.x += w5 * v5.x; a5.y += w5 * v5.y; a5.z += w5 * v5.z; a5.w += w5 * v5.w;
            a6.x += w6 * v6.x; a6.y += w6 * v6.y; a6.z += w6 * v6.z; a6.w += w6 * v6.w;
            a7.x += w7 * v7.x; a7.y += w7 * v7.y; a7.z += w7 * v7.z; a7.w += w7 * v7.w;
        }
        for (; x + 3 <= xhi; x += 4) {
            float w0 = wyv * wxS[x];
            float w1 = wyv * wxS[x + 1];
            float w2 = wyv * wxS[x + 2];
            float w3 = wyv * wxS[x + 3];
            float4 v0 = rowp[(size_t)x * (FC / 4)];
            float4 v1 = rowp[(size_t)(x + 1) * (FC / 4)];
            float4 v2 = rowp[(size_t)(x + 2) * (FC / 4)];
            float4 v3 = rowp[(size_t)(x + 3) * (FC / 4)];
            a0.x += w0 * v0.x; a0.y += w0 * v0.y; a0.z += w0 * v0.z; a0.w += w0 * v0.w;
            a1.x += w1 * v1.x; a1.y += w1 * v1.y; a1.z += w1 * v1.z; a1.w += w1 * v1.w;
            a2.x += w2 * v2.x; a2.y += w2 * v2.y; a2.z += w2 * v2.z; a2.w += w2 * v2.w;
            a3.x += w3 * v3.x; a3.y += w3 * v3.y; a3.z += w3 * v3.z; a3.w += w3 * v3.w;
        }
        for (; x <= xhi; x++) {
            float w0 = wyv * wxS[x];
            float4 v0 = rowp[(size_t)x * (FC / 4)];
            a0.x += w0 * v0.x; a0.y += w0 * v0.y; a0.z += w0 * v0.z; a0.w += w0 * v0.w;
        }
    }
    const float inv = 1.0f / (float)(PP * PP);
    float4 acc;
    acc.x = (((a0.x + a1.x) + (a2.x + a3.x)) + ((a4.x + a5.x) + (a6.x + a7.x))) * inv;
    acc.y = (((a0.y + a1.y) + (a2.y + a3.y)) + ((a4.y + a5.y) + (a6.y + a7.y))) * inv;
    acc.z = (((a0.z + a1.z) + (a2.z + a3.z)) + ((a4.z + a5.z) + (a6.z + a7.z))) * inv;
    acc.w = (((a0.w + a1.w) + (a2.w + a3.w)) + ((a4.w + a5.w) + (a6.w + a7.w))) * inv;
    ((float4*)featvec)[(size_t)gid * (FC / 4) + t] = acc;
}

// ---------------------------------------------------------------------------
// Kernel 2: head GEMM, smem-tiled + split-K.
// grid(16, 8) = (M-tile of 32 props, K-slice of 128), block(256), 64KB smem.
// ---------------------------------------------------------------------------
__global__ void gemm_kernel(const float* __restrict__ featvec,
                            const float* __restrict__ Wc,
                            const float* __restrict__ Wb) {
    extern __shared__ float sm[];
    float* sfS = sm;                 // 32*128
    float* wS = sm + MTILE * KSLICE; // 128*96

    int t = threadIdx.x;
    int p0 = blockIdx.x * MTILE;
    int k0 = blockIdx.y * KSLICE;

    for (int i = t; i < MTILE * KSLICE; i += 256) {
        int p = i >> 7;          // /128
        int k = i & (KSLICE - 1);
        sfS[i] = featvec[(size_t)(p0 + p) * FC + k0 + k];
    }
    for (int i = t; i < KSLICE * NCOL; i += 256) {
        int r = i / NCOL;
        int c = i - r * NCOL;
        float v = 0.0f;
        if (c < NUM_CLASSES + 1) v = Wc[(size_t)(k0 + r) * (NUM_CLASSES + 1) + c];
        else if (c < NUM_CLASSES + 5) v = Wb[(size_t)(k0 + r) * 4 + (c - 81)];
        wS[i] = v;
    }
    __syncthreads();

    int colg = t & 31;
    int propg = t >> 5;              // 0..7
    const float* sfp = sfS + (propg * 4) * KSLICE;

    float a00 = 0.f, a01 = 0.f, a02 = 0.f;
    float a10 = 0.f, a11 = 0.f, a12 = 0.f;
    float a20 = 0.f, a21 = 0.f, a22 = 0.f;
    float a30 = 0.f, a31 = 0.f, a32 = 0.f;

    #pragma unroll 4
    for (int k = 0; k < KSLICE; k++) {
        float w0 = wS[k * NCOL + colg];
        float w1 = wS[k * NCOL + colg + 32];
        float w2 = wS[k * NCOL + colg + 64];
        float s0 = sfp[k];
        float s1 = sfp[KSLICE + k];
        float s2 = sfp[2 * KSLICE + k];
        float s3 = sfp[3 * KSLICE + k];
        a00 += s0 * w0; a01 += s0 * w1; a02 += s0 * w2;
        a10 += s1 * w0; a11 += s1 * w1; a12 += s1 * w2;
        a20 += s2 * w0; a21 += s2 * w1; a22 += s2 * w2;
        a30 += s3 * w0; a31 += s3 * w1; a32 += s3 * w2;
    }

    float* op = g_part + (size_t)blockIdx.y * NPROP * NCOL +
                (size_t)(p0 + propg * 4) * NCOL + colg;
    op[0] = a00; op[32] = a01; op[64] = a02;
    op += NCOL; op[0] = a10; op[32] = a11; op[64] = a12;
    op += NCOL; op[0] = a20; op[32] = a21; op[64] = a22;
    op += NCOL; op[0] = a30; op[32] = a31; op[64] = a32;
}

// ---------------------------------------------------------------------------
// Kernel 3: warp-per-proposal reduce + softmax + decode. grid(128), b(128).
// Lane l owns cols {l, l+32, l+64}; g_part reads coalesced. Softmax via shfl.
// ---------------------------------------------------------------------------
__global__ void reduce_kernel(const float* __restrict__ prop,
                              const float* __restrict__ bc,
                              const float* __restrict__ bb,
                              float* __restrict__ boxes,
                              float* __restrict__ scores) {
    int wid = threadIdx.x >> 5;
    int lane = threadIdx.x & 31;
    int gid = blockIdx.x * 4 + wid;

    float v0 = 0.f, v1 = 0.f, v2 = 0.f;
    #pragma unroll
    for (int ks = 0; ks < KSPLIT; ks++) {
        const float* q = g_part + (size_t)ks * NPROP * NCOL + (size_t)gid * NCOL;
        v0 += q[lane];
        v1 += q[lane + 32];
        v2 += q[lane + 64];
    }
    int c2 = lane + 64;
    v0 += bc[lane];
    v1 += bc[lane + 32];
    if (c2 <= NUM_CLASSES) v2 += bc[c2];
    else if (c2 <= NUM_CLASSES + 4) v2 += bb[c2 - 81];

    float m = fmaxf(fmaxf(v0, v1), (c2 <= NUM_CLASSES) ? v2 : -INFINITY);
    #pragma unroll
    for (int o = 16; o; o >>= 1) m = fmaxf(m, __shfl_xor_sync(0xffffffffu, m, o));

    float e0 = expf(v0 - m);
    float e1 = expf(v1 - m);
    float e2 = (c2 <= NUM_CLASSES) ? expf(v2 - m) : 0.0f;
    float ssum = e0 + e1 + e2;
    #pragma unroll
    for (int o = 16; o; o >>= 1) ssum += __shfl_xor_sync(0xffffffffu, ssum, o);

    float fg = fmaxf(e0, e1);
    if (c2 < NUM_CLASSES) fg = fmaxf(fg, e2);
    #pragma unroll
    for (int o = 16; o; o >>= 1) fg = fmaxf(fg, __shfl_xor_sync(0xffffffffu, fg, o));

    float dx = __shfl_sync(0xffffffffu, v2, 17);   // col 81
    float dy = __shfl_sync(0xffffffffu, v2, 18);   // col 82
    float dwv = __shfl_sync(0xffffffffu, v2, 19);  // col 83
    float dhv = __shfl_sync(0xffffffffu, v2, 20);  // col 84

    if (lane == 0) {
        scores[gid] = fg / ssum;

        const float* p = prop + (size_t)gid * 4;
        float px1 = p[0], py1 = p[1], px2 = p[2], py2 = p[3];
        float wdt = px2 - px1, hgt = py2 - py1;
        float cx = px1 + 0.5f * wdt, cy = py1 + 0.5f * hgt;
        float ddx = dx * 0.1f;
        float ddy = dy * 0.1f;
        float ddw = fminf(dwv * 0.2f, SCALE_CLAMP);
        float ddh = fminf(dhv * 0.2f, SCALE_CLAMP);
        float pcx = ddx * wdt + cx;
        float pcy = ddy * hgt + cy;
        float pw = expf(ddw) * wdt;
        float ph = expf(ddh) * hgt;
        float* ob = boxes + (size_t)gid * 4;
        ob[0] = fminf(fmaxf(pcx - 0.5f * pw, 0.0f), IMG_W);
        ob[1] = fminf(fmaxf(pcy - 0.5f * ph, 0.0f), IMG_H);
        ob[2] = fminf(fmaxf(pcx + 0.5f * pw, 0.0f), IMG_W);
        ob[3] = fminf(fmaxf(pcy + 0.5f * ph, 0.0f), IMG_H);
    }
}

// ---------------------------------------------------------------------------
// Kernel 4a: stable descending sort rank + sorted box gather. grid(2), b(256).
// ---------------------------------------------------------------------------
__global__ void sort_kernel(const float* __restrict__ boxes,
                            const float* __restrict__ scores) {
    int n = blockIdx.x;
    int t = threadIdx.x;
    int gid = n * NR + t;

    __shared__ float ss[NR];
    __shared__ int order[NR];

    float s_i = scores[gid];
    ss[t] = s_i;
    __syncthreads();

    int rk = 0;
    #pragma unroll 8
    for (int j = 0; j < NR; j++) {
        float sj = ss[j];
        rk += (sj > s_i) || (sj == s_i && j < t);
    }
    g_rank[gid] = rk;
    order[rk] = t;
    __syncthreads();

    ((float4*)g_sboxes)[gid] = ((const float4*)boxes)[n * NR + order[t]];
}

// ---------------------------------------------------------------------------
// Kernel 4b: IoU suppression bitmatrix. grid(8, 2), block(256).
// ---------------------------------------------------------------------------
__global__ void iou_kernel() {
    __shared__ float4 sb[NR];
    int n = blockIdx.y;
    int t = threadIdx.x;

    for (int i = t; i < NR; i += 256) sb[i] = ((const float4*)g_sboxes)[n * NR + i];
    __syncthreads();

    int r = blockIdx.x * 32 + (t >> 3);
    int w = t & 7;

    float4 a = sb[r];
    float aa = (a.z - a.x) * (a.w - a.y);
    unsigned int word = 0;
    #pragma unroll 8
    for (int k = 0; k < 32; k++) {
        float4 b = sb[w * 32 + k];
        float ba = (b.z - b.x) * (b.w - b.y);
        float lx = fmaxf(a.x, b.x), ly = fmaxf(a.y, b.y);
        float rx = fminf(a.z, b.z), ry = fminf(a.w, b.w);
        float ww = fmaxf(rx - lx, 0.0f), hh = fmaxf(ry - ly, 0.0f);
        float inter = ww * hh;
        float u = fmaxf(aa + ba - inter, 1e-9f);
        if (inter > NMS_TH * u) word |= (1u << k);
    }
    g_supmask[(n * NR + r) * 8 + w] = word;
}

// ---------------------------------------------------------------------------
// Kernel 4c: greedy + score threshold + stable rank<100 + det write.
// grid(2), block(256). Warp 0 runs the register/ballot greedy.
// ---------------------------------------------------------------------------
__global__ void finish_kernel(const float* __restrict__ boxes,
                              const float* __restrict__ scores,
                              float* __restrict__ det) {
    int n = blockIdx.x;
    int t = threadIdx.x;
    int gid = n * NR + t;

    __shared__ unsigned int keptw[8];
    __shared__ float smask[NR];

    if (t < 32) {
        unsigned kept[8];
        #pragma unroll
        for (int w = 0; w < 8; w++) kept[w] = 0u;
        #pragma unroll
        for (int w = 0; w < 8; w++) {
            int i = w * 32 + t;
            uint4 q0 = *(const uint4*)&g_supmask[(n * NR + i) * 8];
            uint4 q1 = *(const uint4*)&g_supmask[(n * NR + i) * 8 + 4];
            unsigned rw[8] = {q0.x, q0.y, q0.z, q0.w, q1.x, q1.y, q1.z, q1.w};
            unsigned m = 0;
            #pragma unroll
            for (int w2 = 0; w2 < 8; w2++)
                if (w2 < w) m |= rw[w2] & kept[w2];
            bool sup_prev = (m != 0u);
            unsigned myw = rw[w];
            unsigned kw = 0u;
            #pragma unroll
            for (int k = 0; k < 32; k++) {
                bool keep_me = (!sup_prev) && ((myw & kw) == 0u);
                unsigned b = __ballot_sync(0xffffffffu, keep_me);
                kw |= (b & (1u << k));
            }
            kept[w] = kw;
        }
        #pragma unroll
        for (int w = 0; w < 8; w++)
            if (t == w) keptw[w] = kept[w];
    }

    float s_i = scores[gid];
    int rk = g_rank[gid];
    __syncthreads();

    bool kp = (keptw[rk >> 5] >> (rk & 31)) & 1u;
    kp = kp && (s_i > SCORE_TH);
    smask[t] = kp ? s_i : -INFINITY;
    __syncthreads();

    int rank2 = 0;
    float mi = smask[t];
    #pragma unroll 8
    for (int j = 0; j < NR; j++) {
        float mj = smask[j];
        rank2 += (mj > mi) || (mj == mi && j < t);
    }
    kp = kp && (rank2 < MAX_DET);

    const float* bsrc = boxes + (size_t)gid * 4;
    float* drow = det + (size_t)gid * 6;
    drow[0] = bsrc[0]; drow[1] = bsrc[1];
    drow[2] = bsrc[2]; drow[3] = bsrc[3];
    drow[4] = s_i;
    drow[5] = kp ? 1.0f : 0.0f;
}

// ---------------------------------------------------------------------------
extern "C" void kernel_launch(void* const* d_in, const int* in_sizes, int n_in,
                              void* d_out, int out_size) {
    const float* features = (const float*)d_in[0];
    const float* proposals = (const float*)d_in[1];
    const float* gt_boxes = (const float*)d_in[2];
    // d_in[3] = gt_classes (unused by reference)
    const float* W_cls = (const float*)d_in[4];
    const float* b_cls = (const float*)d_in[5];
    const float* W_box = (const float*)d_in[6];
    const float* b_box = (const float*)d_in[7];

    float* out = (float*)d_out;
    float* det = out;                          // 2*256*6 = 3072
    float* out_idx = out + NIMG * NR * 6;      // 512
    float* out_lbl = out_idx + NIMG * NR;      // 512

    float* featvec; cudaGetSymbolAddress((void**)&featvec, g_featvec);
    float* boxes;   cudaGetSymbolAddress((void**)&boxes, g_boxes);
    float* scores;  cudaGetSymbolAddress((void**)&scores, g_scores);

    const int GEMM_SMEM = (MTILE * KSLICE + KSLICE * NCOL) * 4;    // 65536 B
    cudaFuncSetAttribute(gemm_kernel,
                         cudaFuncAttributeMaxDynamicSharedMemorySize, GEMM_SMEM);

    roi_kernel<<<dim3(NR, NIMG), 256>>>(features, proposals, gt_boxes,
                                        featvec, out_idx, out_lbl);
    gemm_kernel<<<dim3(NPROP / MTILE, KSPLIT), 256, GEMM_SMEM>>>(featvec,
                                                                 W_cls, W_box);
    reduce_kernel<<<NPROP / 4, 128>>>(proposals, b_cls, b_box, boxes, scores);
    sort_kernel<<<NIMG, NR>>>(boxes, scores);
    iou_kernel<<<dim3(8, NIMG), 256>>>();
    finish_kernel<<<NIMG, NR>>>(boxes, scores, det);
}

// round 13
// speedup vs baseline: 1.0973x; 1.0973x over previous
#include <cuda_runtime.h>
#include <math.h>

#define IMG_H 800.0f
#define IMG_W 1280.0f
#define FSCALE (1.0f/16.0f)
#define PP 14
#define NUM_CLASSES 80
#define SCORE_TH 0.05f
#define NMS_TH 0.5f
#define MAX_DET 100
#define IOU_TH 0.5f
#define SCALE_CLAMP 4.135166556742356f
#define FH 50
#define FW 80
#define FC 1024
#define NIMG 2
#define NR 256
#define NGT 64
#define NPROP (NIMG * NR)          // 512
#define NCOL 96                    // padded output cols: 0..80 cls, 81..84 box
#define KSPLIT 8
#define KSLICE (FC / KSPLIT)       // 128
#define MTILE 32

// Scratch (device globals; no allocation allowed)
__device__ float g_featvec[NPROP * FC];
__device__ float g_boxes[NPROP * 4];
__device__ float g_scores[NPROP];
__device__ float g_wy[NPROP * FH];
__device__ float g_wx[NPROP * FW];
__device__ int   g_bnd[NPROP * 4];               // ylo,yhi,xlo,xhi
__device__ float g_part[KSPLIT * NPROP * NCOL];  // split-K partials
__device__ float g_sboxes[NPROP * 4];            // score-sorted boxes
__device__ int   g_rank[NPROP];                  // sorted position per proposal
__device__ unsigned int g_supmask[NPROP * 8];    // suppression bitmatrix
__device__ unsigned int g_keptw[NIMG * 8];       // greedy kept bits

// ---------------------------------------------------------------------------
// Kernel 1: fused match + separable ROIAlign weight tables.
// grid(8, 2): 32 boxes per block, block(256). Per box: sub 0 = y-table,
// sub 1 = x-table, sub 2 = GT matching (all independent).
// ---------------------------------------------------------------------------
__global__ void weight_kernel(const float* __restrict__ prop,
                              const float* __restrict__ gt,
                              float* __restrict__ out_idx,
                              float* __restrict__ out_lbl) {
    int n = blockIdx.y;
    int b0 = blockIdx.x * 32;
    int t = threadIdx.x;

    __shared__ float wy[32 * FH];
    __shared__ float wx[32 * FW];

    for (int i = t; i < 32 * FH; i += 256) wy[i] = 0.0f;
    for (int i = t; i < 32 * FW; i += 256) wx[i] = 0.0f;
    __syncthreads();

    int b = t >> 3;          // box within block
    int sub = t & 7;
    int box = b0 + b;
    const float* p = prop + (n * NR + box) * 4;

    if (sub == 0) {
        float y1 = p[1] * FSCALE, y2 = p[3] * FSCALE;
        float bh = (y2 - y1) * (1.0f / (float)PP);
        int lo = FH, hi = 0;
        for (int py = 0; py < PP; py++) {
            float gy = y1 + ((float)py + 0.5f) * bh - 0.5f;
            gy = fminf(fmaxf(gy, 0.0f), (float)(FH - 1));
            float y0 = floorf(gy);
            int y0i = (int)y0;
            int y1i = min(y0i + 1, FH - 1);
            float ly = gy - y0;
            wy[b * FH + y0i] += 1.0f - ly;
            wy[b * FH + y1i] += ly;
            lo = min(lo, y0i);
            hi = max(hi, y1i);
        }
        g_bnd[(n * NR + box) * 4 + 0] = lo;
        g_bnd[(n * NR + box) * 4 + 1] = hi;
    } else if (sub == 1) {
        float x1 = p[0] * FSCALE, x2 = p[2] * FSCALE;
        float bw = (x2 - x1) * (1.0f / (float)PP);
        int lo = FW, hi = 0;
        for (int px = 0; px < PP; px++) {
            float gx = x1 + ((float)px + 0.5f) * bw - 0.5f;
            gx = fminf(fmaxf(gx, 0.0f), (float)(FW - 1));
            float x0 = floorf(gx);
            int x0i = (int)x0;
            int x1i = min(x0i + 1, FW - 1);
            float lx = gx - x0;
            wx[b * FW + x0i] += 1.0f - lx;
            wx[b * FW + x1i] += lx;
            lo = min(lo, x0i);
            hi = max(hi, x1i);
        }
        g_bnd[(n * NR + box) * 4 + 2] = lo;
        g_bnd[(n * NR + box) * 4 + 3] = hi;
    } else if (sub == 2) {
        float px1 = p[0], py1 = p[1], px2 = p[2], py2 = p[3];
        float pa = (px2 - px1) * (py2 - py1);
        float best = -1.0f;
        int bi = 0;
        for (int g = 0; g < NGT; g++) {
            const float* gb = gt + (n * NGT + g) * 4;
            float gx1 = gb[0], gy1 = gb[1], gx2 = gb[2], gy2 = gb[3];
            float ga = (gx2 - gx1) * (gy2 - gy1);
            float lx = fmaxf(gx1, px1), ly = fmaxf(gy1, py1);
            float rx = fminf(gx2, px2), ry = fminf(gy2, py2);
            float w = fmaxf(rx - lx, 0.0f), h = fmaxf(ry - ly, 0.0f);
            float inter = w * h;
            float iou = inter / fmaxf(ga + pa - inter, 1e-9f);
            if (iou > best) { best = iou; bi = g; }
        }
        out_idx[n * NR + box] = (float)bi;
        out_lbl[n * NR + box] = (best >= IOU_TH) ? 1.0f : 0.0f;
    }
    __syncthreads();

    for (int i = t; i < 32 * FH; i += 256) g_wy[(n * NR + b0) * FH + i] = wy[i];
    for (int i = t; i < 32 * FW; i += 256) g_wx[(n * NR + b0) * FW + i] = wx[i];
}

// ---------------------------------------------------------------------------
// Kernel 2: ROIAlign, one block per box (R11 known-good). grid(256, 2), b(256).
// Thread t owns channels [4t, 4t+4). Weight tables in smem (broadcast reads);
// feature reads are coalesced LDG.128. 4-wide x-unroll, 4 accumulator sets.
// ---------------------------------------------------------------------------
__global__ void roi_kernel(const float* __restrict__ feat,
                           float* __restrict__ featvec) {
    __shared__ float wyS[FH];
    __shared__ float wxS[FW];
    __shared__ int bndS[4];

    int box = blockIdx.x;
    int n = blockIdx.y;
    int gid = n * NR + box;
    int t = threadIdx.x;

    if (t < FH) wyS[t] = g_wy[gid * FH + t];
    if (t >= 64 && t < 64 + FW) wxS[t - 64] = g_wx[gid * FW + (t - 64)];
    if (t >= 160 && t < 164) bndS[t - 160] = g_bnd[gid * 4 + (t - 160)];
    __syncthreads();

    int ylo = bndS[0], yhi = bndS[1], xlo = bndS[2], xhi = bndS[3];

    const float4* f = (const float4*)(feat + (size_t)n * FH * FW * FC) + t;
    float4 aA = make_float4(0.f, 0.f, 0.f, 0.f);
    float4 aB = make_float4(0.f, 0.f, 0.f, 0.f);
    float4 aC = make_float4(0.f, 0.f, 0.f, 0.f);
    float4 aD = make_float4(0.f, 0.f, 0.f, 0.f);

    for (int y = ylo; y <= yhi; y++) {
        float wyv = wyS[y];
        const float4* rowp = f + (size_t)(y * FW) * (FC / 4);
        int x = xlo;
        for (; x + 3 <= xhi; x += 4) {
            float wa = wyv * wxS[x];
            float wb = wyv * wxS[x + 1];
            float wc = wyv * wxS[x + 2];
            float wd = wyv * wxS[x + 3];
            float4 va = rowp[(size_t)x * (FC / 4)];
            float4 vb = rowp[(size_t)(x + 1) * (FC / 4)];
            float4 vc = rowp[(size_t)(x + 2) * (FC / 4)];
            float4 vd = rowp[(size_t)(x + 3) * (FC / 4)];
            aA.x += wa * va.x; aA.y += wa * va.y; aA.z += wa * va.z; aA.w += wa * va.w;
            aB.x += wb * vb.x; aB.y += wb * vb.y; aB.z += wb * vb.z; aB.w += wb * vb.w;
            aC.x += wc * vc.x; aC.y += wc * vc.y; aC.z += wc * vc.z; aC.w += wc * vc.w;
            aD.x += wd * vd.x; aD.y += wd * vd.y; aD.z += wd * vd.z; aD.w += wd * vd.w;
        }
        for (; x <= xhi; x++) {
            float wa = wyv * wxS[x];
            float4 va = rowp[(size_t)x * (FC / 4)];
            aA.x += wa * va.x; aA.y += wa * va.y; aA.z += wa * va.z; aA.w += wa * va.w;
        }
    }
    const float inv = 1.0f / (float)(PP * PP);
    float4 acc;
    acc.x = ((aA.x + aB.x) + (aC.x + aD.x)) * inv;
    acc.y = ((aA.y + aB.y) + (aC.y + aD.y)) * inv;
    acc.z = ((aA.z + aB.z) + (aC.z + aD.z)) * inv;
    acc.w = ((aA.w + aB.w) + (aC.w + aD.w)) * inv;
    ((float4*)featvec)[(size_t)gid * (FC / 4) + t] = acc;
}

// ---------------------------------------------------------------------------
// Kernel 3a: head GEMM, smem-tiled + split-K.
// grid(16, 8) = (M-tile of 32 props, K-slice of 128), block(256), 64KB smem.
// ---------------------------------------------------------------------------
__global__ void gemm_kernel(const float* __restrict__ featvec,
                            const float* __restrict__ Wc,
                            const float* __restrict__ Wb) {
    extern __shared__ float sm[];
    float* sfS = sm;                 // 32*128
    float* wS = sm + MTILE * KSLICE; // 128*96

    int t = threadIdx.x;
    int p0 = blockIdx.x * MTILE;
    int k0 = blockIdx.y * KSLICE;

    for (int i = t; i < MTILE * KSLICE; i += 256) {
        int p = i >> 7;          // /128
        int k = i & (KSLICE - 1);
        sfS[i] = featvec[(size_t)(p0 + p) * FC + k0 + k];
    }
    for (int i = t; i < KSLICE * NCOL; i += 256) {
        int r = i / NCOL;
        int c = i - r * NCOL;
        float v = 0.0f;
        if (c < NUM_CLASSES + 1) v = Wc[(size_t)(k0 + r) * (NUM_CLASSES + 1) + c];
        else if (c < NUM_CLASSES + 5) v = Wb[(size_t)(k0 + r) * 4 + (c - 81)];
        wS[i] = v;
    }
    __syncthreads();

    int colg = t & 31;
    int propg = t >> 5;              // 0..7
    const float* sfp = sfS + (propg * 4) * KSLICE;

    float a00 = 0.f, a01 = 0.f, a02 = 0.f;
    float a10 = 0.f, a11 = 0.f, a12 = 0.f;
    float a20 = 0.f, a21 = 0.f, a22 = 0.f;
    float a30 = 0.f, a31 = 0.f, a32 = 0.f;

    #pragma unroll 4
    for (int k = 0; k < KSLICE; k++) {
        float w0 = wS[k * NCOL + colg];
        float w1 = wS[k * NCOL + colg + 32];
        float w2 = wS[k * NCOL + colg + 64];
        float s0 = sfp[k];
        float s1 = sfp[KSLICE + k];
        float s2 = sfp[2 * KSLICE + k];
        float s3 = sfp[3 * KSLICE + k];
        a00 += s0 * w0; a01 += s0 * w1; a02 += s0 * w2;
        a10 += s1 * w0; a11 += s1 * w1; a12 += s1 * w2;
        a20 += s2 * w0; a21 += s2 * w1; a22 += s2 * w2;
        a30 += s3 * w0; a31 += s3 * w1; a32 += s3 * w2;
    }

    float* op = g_part + (size_t)blockIdx.y * NPROP * NCOL +
                (size_t)(p0 + propg * 4) * NCOL + colg;
    op[0] = a00; op[32] = a01; op[64] = a02;
    op += NCOL; op[0] = a10; op[32] = a11; op[64] = a12;
    op += NCOL; op[0] = a20; op[32] = a21; op[64] = a22;
    op += NCOL; op[0] = a30; op[32] = a31; op[64] = a32;
}

// ---------------------------------------------------------------------------
// Kernel 3b: warp-per-proposal reduce + softmax + decode. grid(128), b(128).
// ---------------------------------------------------------------------------
__global__ void reduce_kernel(const float* __restrict__ prop,
                              const float* __restrict__ bc,
                              const float* __restrict__ bb,
                              float* __restrict__ boxes,
                              float* __restrict__ scores) {
    int wid = threadIdx.x >> 5;
    int lane = threadIdx.x & 31;
    int gid = blockIdx.x * 4 + wid;

    float v0 = 0.f, v1 = 0.f, v2 = 0.f;
    #pragma unroll
    for (int ks = 0; ks < KSPLIT; ks++) {
        const float* q = g_part + (size_t)ks * NPROP * NCOL + (size_t)gid * NCOL;
        v0 += q[lane];
        v1 += q[lane + 32];
        v2 += q[lane + 64];
    }
    int c2 = lane + 64;
    v0 += bc[lane];
    v1 += bc[lane + 32];
    if (c2 <= NUM_CLASSES) v2 += bc[c2];
    else if (c2 <= NUM_CLASSES + 4) v2 += bb[c2 - 81];

    float m = fmaxf(fmaxf(v0, v1), (c2 <= NUM_CLASSES) ? v2 : -INFINITY);
    #pragma unroll
    for (int o = 16; o; o >>= 1) m = fmaxf(m, __shfl_xor_sync(0xffffffffu, m, o));

    float e0 = expf(v0 - m);
    float e1 = expf(v1 - m);
    float e2 = (c2 <= NUM_CLASSES) ? expf(v2 - m) : 0.0f;
    float ssum = e0 + e1 + e2;
    #pragma unroll
    for (int o = 16; o; o >>= 1) ssum += __shfl_xor_sync(0xffffffffu, ssum, o);

    float fg = fmaxf(e0, e1);
    if (c2 < NUM_CLASSES) fg = fmaxf(fg, e2);
    #pragma unroll
    for (int o = 16; o; o >>= 1) fg = fmaxf(fg, __shfl_xor_sync(0xffffffffu, fg, o));

    float dx = __shfl_sync(0xffffffffu, v2, 17);   // col 81
    float dy = __shfl_sync(0xffffffffu, v2, 18);   // col 82
    float dwv = __shfl_sync(0xffffffffu, v2, 19);  // col 83
    float dhv = __shfl_sync(0xffffffffu, v2, 20);  // col 84

    if (lane == 0) {
        scores[gid] = fg / ssum;

        const float* p = prop + (size_t)gid * 4;
        float px1 = p[0], py1 = p[1], px2 = p[2], py2 = p[3];
        float wdt = px2 - px1, hgt = py2 - py1;
        float cx = px1 + 0.5f * wdt, cy = py1 + 0.5f * hgt;
        float ddx = dx * 0.1f;
        float ddy = dy * 0.1f;
        float ddw = fminf(dwv * 0.2f, SCALE_CLAMP);
        float ddh = fminf(dhv * 0.2f, SCALE_CLAMP);
        float pcx = ddx * wdt + cx;
        float pcy = ddy * hgt + cy;
        float pw = expf(ddw) * wdt;
        float ph = expf(ddh) * hgt;
        float* ob = boxes + (size_t)gid * 4;
        ob[0] = fminf(fmaxf(pcx - 0.5f * pw, 0.0f), IMG_W);
        ob[1] = fminf(fmaxf(pcy - 0.5f * ph, 0.0f), IMG_H);
        ob[2] = fminf(fmaxf(pcx + 0.5f * pw, 0.0f), IMG_W);
        ob[3] = fminf(fmaxf(pcy + 0.5f * ph, 0.0f), IMG_H);
    }
}

// ---------------------------------------------------------------------------
// Kernel 4a: warp-per-proposal stable descending rank + sorted-box scatter.
// grid(32, 2), block(256) = 8 warps = 8 proposals. Lane l counts its 8 j's;
// rank via shfl sum (order-independent count -> identical to serial version).
// ---------------------------------------------------------------------------
__global__ void sort_kernel(const float* __restrict__ boxes,
                            const float* __restrict__ scores) {
    int n = blockIdx.y;
    int i = blockIdx.x * 8 + (threadIdx.x >> 5);
    int lane = threadIdx.x & 31;
    int gid = n * NR + i;

    float s_i = scores[gid];
    int cnt = 0;
    #pragma unroll
    for (int jj = 0; jj < 8; jj++) {
        int j = lane + jj * 32;
        float sj = scores[n * NR + j];
        cnt += (sj > s_i) || (sj == s_i && j < i);
    }
    #pragma unroll
    for (int o = 16; o; o >>= 1) cnt += __shfl_xor_sync(0xffffffffu, cnt, o);

    if (lane == 0) {
        g_rank[gid] = cnt;
        ((float4*)g_sboxes)[n * NR + cnt] = ((const float4*)boxes)[gid];
    }
}

// ---------------------------------------------------------------------------
// Kernel 4b: IoU suppression bitmatrix. grid(8, 2), block(256).
// ---------------------------------------------------------------------------
__global__ void iou_kernel() {
    __shared__ float4 sb[NR];
    int n = blockIdx.y;
    int t = threadIdx.x;

    for (int i = t; i < NR; i += 256) sb[i] = ((const float4*)g_sboxes)[n * NR + i];
    __syncthreads();

    int r = blockIdx.x * 32 + (t >> 3);
    int w = t & 7;

    float4 a = sb[r];
    float aa = (a.z - a.x) * (a.w - a.y);
    unsigned int word = 0;
    #pragma unroll 8
    for (int k = 0; k < 32; k++) {
        float4 b = sb[w * 32 + k];
        float ba = (b.z - b.x) * (b.w - b.y);
        float lx = fmaxf(a.x, b.x), ly = fmaxf(a.y, b.y);
        float rx = fminf(a.z, b.z), ry = fminf(a.w, b.w);
        float ww = fmaxf(rx - lx, 0.0f), hh = fmaxf(ry - ly, 0.0f);
        float inter = ww * hh;
        float u = fmaxf(aa + ba - inter, 1e-9f);
        if (inter > NMS_TH * u) word |= (1u << k);
    }
    g_supmask[(n * NR + r) * 8 + w] = word;
}

// ---------------------------------------------------------------------------
// Kernel 4c: greedy only. grid(2), block(32). Register/ballot greedy over the
// bitmatrix; writes the 8 kept-words to global.
// ---------------------------------------------------------------------------
__global__ void greedy_kernel() {
    int n = blockIdx.x;
    int t = threadIdx.x;

    unsigned kept[8];
    #pragma unroll
    for (int w = 0; w < 8; w++) kept[w] = 0u;
    #pragma unroll
    for (int w = 0; w < 8; w++) {
        int i = w * 32 + t;
        uint4 q0 = *(const uint4*)&g_supmask[(n * NR + i) * 8];
        uint4 q1 = *(const uint4*)&g_supmask[(n * NR + i) * 8 + 4];
        unsigned rw[8] = {q0.x, q0.y, q0.z, q0.w, q1.x, q1.y, q1.z, q1.w};
        unsigned m = 0;
        #pragma unroll
        for (int w2 = 0; w2 < 8; w2++)
            if (w2 < w) m |= rw[w2] & kept[w2];
        bool sup_prev = (m != 0u);
        unsigned myw = rw[w];
        unsigned kw = 0u;
        #pragma unroll
        for (int k = 0; k < 32; k++) {
            bool keep_me = (!sup_prev) && ((myw & kw) == 0u);
            unsigned b = __ballot_sync(0xffffffffu, keep_me);
            kw |= (b & (1u << k));
        }
        kept[w] = kw;
    }
    if (t < 8) g_keptw[n * 8 + t] = kept[t];
}

// ---------------------------------------------------------------------------
// Kernel 4d: warp-per-proposal rank<100 + det write. grid(32, 2), block(256).
// smask value for any j computed on the fly from keptw/rank/scores.
// ---------------------------------------------------------------------------
__global__ void finish_kernel(const float* __restrict__ boxes,
                              const float* __restrict__ scores,
                              float* __restrict__ det) {
    __shared__ unsigned int keptS[8];
    int n = blockIdx.y;
    int i = blockIdx.x * 8 + (threadIdx.x >> 5);
    int lane = threadIdx.x & 31;
    int gid = n * NR + i;

    if (threadIdx.x < 8) keptS[threadIdx.x] = g_keptw[n * 8 + threadIdx.x];
    __syncthreads();

    float s_i = scores[gid];
    int rk = g_rank[gid];
    bool kp = (keptS[rk >> 5] >> (rk & 31)) & 1u;
    kp = kp && (s_i > SCORE_TH);
    float mi = kp ? s_i : -INFINITY;

    int cnt = 0;
    #pragma unroll
    for (int jj = 0; jj < 8; jj++) {
        int j = lane + jj * 32;
        int gj = n * NR + j;
        float sj = scores[gj];
        int rj = g_rank[gj];
        bool kj = (keptS[rj >> 5] >> (rj & 31)) & 1u;
        kj = kj && (sj > SCORE_TH);
        float mj = kj ? sj : -INFINITY;
        cnt += (mj > mi) || (mj == mi && j < i);
    }
    #pragma unroll
    for (int o = 16; o; o >>= 1) cnt += __shfl_xor_sync(0xffffffffu, cnt, o);

    if (lane == 0) {
        kp = kp && (cnt < MAX_DET);
        const float* bsrc = boxes + (size_t)gid * 4;
        float* drow = det + (size_t)gid * 6;
        drow[0] = bsrc[0]; drow[1] = bsrc[1];
        drow[2] = bsrc[2]; drow[3] = bsrc[3];
        drow[4] = s_i;
        drow[5] = kp ? 1.0f : 0.0f;
    }
}

// ---------------------------------------------------------------------------
extern "C" void kernel_launch(void* const* d_in, const int* in_sizes, int n_in,
                              void* d_out, int out_size) {
    const float* features = (const float*)d_in[0];
    const float* proposals = (const float*)d_in[1];
    const float* gt_boxes = (const float*)d_in[2];
    // d_in[3] = gt_classes (unused by reference)
    const float* W_cls = (const float*)d_in[4];
    const float* b_cls = (const float*)d_in[5];
    const float* W_box = (const float*)d_in[6];
    const float* b_box = (const float*)d_in[7];

    float* out = (float*)d_out;
    float* det = out;                          // 2*256*6 = 3072
    float* out_idx = out + NIMG * NR * 6;      // 512
    float* out_lbl = out_idx + NIMG * NR;      // 512

    float* featvec; cudaGetSymbolAddress((void**)&featvec, g_featvec);
    float* boxes;   cudaGetSymbolAddress((void**)&boxes, g_boxes);
    float* scores;  cudaGetSymbolAddress((void**)&scores, g_scores);

    const int GEMM_SMEM = (MTILE * KSLICE + KSLICE * NCOL) * 4;    // 65536 B
    cudaFuncSetAttribute(gemm_kernel,
                         cudaFuncAttributeMaxDynamicSharedMemorySize, GEMM_SMEM);

    weight_kernel<<<dim3(8, NIMG), 256>>>(proposals, gt_boxes, out_idx, out_lbl);
    roi_kernel<<<dim3(NR, NIMG), 256>>>(features, featvec);
    gemm_kernel<<<dim3(NPROP / MTILE, KSPLIT), 256, GEMM_SMEM>>>(featvec,
                                                                 W_cls, W_box);
    reduce_kernel<<<NPROP / 4, 128>>>(proposals, b_cls, b_box, boxes, scores);
    sort_kernel<<<dim3(NR / 8, NIMG), 256>>>(boxes, scores);
    iou_kernel<<<dim3(8, NIMG), 256>>>();
    greedy_kernel<<<NIMG, 32>>>();
    finish_kernel<<<dim3(NR / 8, NIMG), 256>>>(boxes, scores, det);
}

// round 14
// speedup vs baseline: 1.1518x; 1.0497x over previous
#include <cuda_runtime.h>
#include <math.h>

#define IMG_H 800.0f
#define IMG_W 1280.0f
#define FSCALE (1.0f/16.0f)
#define PP 14
#define NUM_CLASSES 80
#define SCORE_TH 0.05f
#define NMS_TH 0.5f
#define MAX_DET 100
#define IOU_TH 0.5f
#define SCALE_CLAMP 4.135166556742356f
#define FH 50
#define FW 80
#define FC 1024
#define NIMG 2
#define NR 256
#define NGT 64
#define NPROP (NIMG * NR)          // 512
#define NCOL 96                    // padded output cols: 0..80 cls, 81..84 box
#define KSPLIT 8
#define KSLICE (FC / KSPLIT)       // 128
#define MTILE 32

// Scratch (device globals; no allocation allowed)
__device__ float g_featvec[NPROP * FC];
__device__ float g_boxes[NPROP * 4];
__device__ float g_scores[NPROP];
__device__ float g_part[KSPLIT * NPROP * NCOL];  // split-K partials
__device__ float g_sboxes[NPROP * 4];            // score-sorted boxes
__device__ int   g_rank[NPROP];                  // sorted position per proposal
__device__ unsigned int g_supmask[NPROP * 8];    // suppression bitmatrix

// ---------------------------------------------------------------------------
// Kernel 1: ROIAlign + fused weight-table build + fused GT matching.
// grid(256, 2) = (box, image), block(256). Prologue: thread 0 builds the
// separable y-weight table in smem, thread 32 the x-table, thread 64 does
// this box's GT match. Body (bit-identical to R13): thread t owns channels
// [4t,4t+4), 4-wide x-unroll with 4 independent accumulator sets.
// ---------------------------------------------------------------------------
__global__ void roi_kernel(const float* __restrict__ feat,
                           const float* __restrict__ prop,
                           const float* __restrict__ gt,
                           float* __restrict__ featvec,
                           float* __restrict__ out_idx,
                           float* __restrict__ out_lbl) {
    __shared__ float wyS[FH];
    __shared__ float wxS[FW];
    __shared__ int bndS[4];

    int box = blockIdx.x;
    int n = blockIdx.y;
    int gid = n * NR + box;
    int t = threadIdx.x;

    if (t < FH) wyS[t] = 0.0f;
    if (t >= 64 && t < 64 + FW) wxS[t - 64] = 0.0f;
    __syncthreads();

    const float* p = prop + (size_t)gid * 4;

    if (t == 0) {
        float y1 = p[1] * FSCALE, y2 = p[3] * FSCALE;
        float bh = (y2 - y1) * (1.0f / (float)PP);
        int lo = FH, hi = 0;
        for (int py = 0; py < PP; py++) {
            float gy = y1 + ((float)py + 0.5f) * bh - 0.5f;
            gy = fminf(fmaxf(gy, 0.0f), (float)(FH - 1));
            float y0 = floorf(gy);
            int y0i = (int)y0;
            int y1i = min(y0i + 1, FH - 1);
            float ly = gy - y0;
            wyS[y0i] += 1.0f - ly;
            wyS[y1i] += ly;
            lo = min(lo, y0i);
            hi = max(hi, y1i);
        }
        bndS[0] = lo; bndS[1] = hi;
    } else if (t == 32) {
        float x1 = p[0] * FSCALE, x2 = p[2] * FSCALE;
        float bw = (x2 - x1) * (1.0f / (float)PP);
        int lo = FW, hi = 0;
        for (int px = 0; px < PP; px++) {
            float gx = x1 + ((float)px + 0.5f) * bw - 0.5f;
            gx = fminf(fmaxf(gx, 0.0f), (float)(FW - 1));
            float x0 = floorf(gx);
            int x0i = (int)x0;
            int x1i = min(x0i + 1, FW - 1);
            float lx = gx - x0;
            wxS[x0i] += 1.0f - lx;
            wxS[x1i] += lx;
            lo = min(lo, x0i);
            hi = max(hi, x1i);
        }
        bndS[2] = lo; bndS[3] = hi;
    } else if (t == 64) {
        float px1 = p[0], py1 = p[1], px2 = p[2], py2 = p[3];
        float pa = (px2 - px1) * (py2 - py1);
        float best = -1.0f;
        int bi = 0;
        for (int g = 0; g < NGT; g++) {
            const float* gb = gt + (n * NGT + g) * 4;
            float gx1 = gb[0], gy1 = gb[1], gx2 = gb[2], gy2 = gb[3];
            float ga = (gx2 - gx1) * (gy2 - gy1);
            float lx = fmaxf(gx1, px1), ly = fmaxf(gy1, py1);
            float rx = fminf(gx2, px2), ry = fminf(gy2, py2);
            float w = fmaxf(rx - lx, 0.0f), h = fmaxf(ry - ly, 0.0f);
            float inter = w * h;
            float iou = inter / fmaxf(ga + pa - inter, 1e-9f);
            if (iou > best) { best = iou; bi = g; }
        }
        out_idx[gid] = (float)bi;
        out_lbl[gid] = (best >= IOU_TH) ? 1.0f : 0.0f;
    }
    __syncthreads();

    int ylo = bndS[0], yhi = bndS[1], xlo = bndS[2], xhi = bndS[3];

    const float4* f = (const float4*)(feat + (size_t)n * FH * FW * FC) + t;
    float4 aA = make_float4(0.f, 0.f, 0.f, 0.f);
    float4 aB = make_float4(0.f, 0.f, 0.f, 0.f);
    float4 aC = make_float4(0.f, 0.f, 0.f, 0.f);
    float4 aD = make_float4(0.f, 0.f, 0.f, 0.f);

    for (int y = ylo; y <= yhi; y++) {
        float wyv = wyS[y];
        const float4* rowp = f + (size_t)(y * FW) * (FC / 4);
        int x = xlo;
        for (; x + 3 <= xhi; x += 4) {
            float wa = wyv * wxS[x];
            float wb = wyv * wxS[x + 1];
            float wc = wyv * wxS[x + 2];
            float wd = wyv * wxS[x + 3];
            float4 va = rowp[(size_t)x * (FC / 4)];
            float4 vb = rowp[(size_t)(x + 1) * (FC / 4)];
            float4 vc = rowp[(size_t)(x + 2) * (FC / 4)];
            float4 vd = rowp[(size_t)(x + 3) * (FC / 4)];
            aA.x += wa * va.x; aA.y += wa * va.y; aA.z += wa * va.z; aA.w += wa * va.w;
            aB.x += wb * vb.x; aB.y += wb * vb.y; aB.z += wb * vb.z; aB.w += wb * vb.w;
            aC.x += wc * vc.x; aC.y += wc * vc.y; aC.z += wc * vc.z; aC.w += wc * vc.w;
            aD.x += wd * vd.x; aD.y += wd * vd.y; aD.z += wd * vd.z; aD.w += wd * vd.w;
        }
        for (; x <= xhi; x++) {
            float wa = wyv * wxS[x];
            float4 va = rowp[(size_t)x * (FC / 4)];
            aA.x += wa * va.x; aA.y += wa * va.y; aA.z += wa * va.z; aA.w += wa * va.w;
        }
    }
    const float inv = 1.0f / (float)(PP * PP);
    float4 acc;
    acc.x = ((aA.x + aB.x) + (aC.x + aD.x)) * inv;
    acc.y = ((aA.y + aB.y) + (aC.y + aD.y)) * inv;
    acc.z = ((aA.z + aB.z) + (aC.z + aD.z)) * inv;
    acc.w = ((aA.w + aB.w) + (aC.w + aD.w)) * inv;
    ((float4*)featvec)[(size_t)gid * (FC / 4) + t] = acc;
}

// ---------------------------------------------------------------------------
// Kernel 2: head GEMM, smem-tiled + split-K.
// grid(16, 8) = (M-tile of 32 props, K-slice of 128), block(256), 64KB smem.
// ---------------------------------------------------------------------------
__global__ void gemm_kernel(const float* __restrict__ featvec,
                            const float* __restrict__ Wc,
                            const float* __restrict__ Wb) {
    extern __shared__ float sm[];
    float* sfS = sm;                 // 32*128
    float* wS = sm + MTILE * KSLICE; // 128*96

    int t = threadIdx.x;
    int p0 = blockIdx.x * MTILE;
    int k0 = blockIdx.y * KSLICE;

    for (int i = t; i < MTILE * KSLICE; i += 256) {
        int p = i >> 7;          // /128
        int k = i & (KSLICE - 1);
        sfS[i] = featvec[(size_t)(p0 + p) * FC + k0 + k];
    }
    for (int i = t; i < KSLICE * NCOL; i += 256) {
        int r = i / NCOL;
        int c = i - r * NCOL;
        float v = 0.0f;
        if (c < NUM_CLASSES + 1) v = Wc[(size_t)(k0 + r) * (NUM_CLASSES + 1) + c];
        else if (c < NUM_CLASSES + 5) v = Wb[(size_t)(k0 + r) * 4 + (c - 81)];
        wS[i] = v;
    }
    __syncthreads();

    int colg = t & 31;
    int propg = t >> 5;              // 0..7
    const float* sfp = sfS + (propg * 4) * KSLICE;

    float a00 = 0.f, a01 = 0.f, a02 = 0.f;
    float a10 = 0.f, a11 = 0.f, a12 = 0.f;
    float a20 = 0.f, a21 = 0.f, a22 = 0.f;
    float a30 = 0.f, a31 = 0.f, a32 = 0.f;

    #pragma unroll 4
    for (int k = 0; k < KSLICE; k++) {
        float w0 = wS[k * NCOL + colg];
        float w1 = wS[k * NCOL + colg + 32];
        float w2 = wS[k * NCOL + colg + 64];
        float s0 = sfp[k];
        float s1 = sfp[KSLICE + k];
        float s2 = sfp[2 * KSLICE + k];
        float s3 = sfp[3 * KSLICE + k];
        a00 += s0 * w0; a01 += s0 * w1; a02 += s0 * w2;
        a10 += s1 * w0; a11 += s1 * w1; a12 += s1 * w2;
        a20 += s2 * w0; a21 += s2 * w1; a22 += s2 * w2;
        a30 += s3 * w0; a31 += s3 * w1; a32 += s3 * w2;
    }

    float* op = g_part + (size_t)blockIdx.y * NPROP * NCOL +
                (size_t)(p0 + propg * 4) * NCOL + colg;
    op[0] = a00; op[32] = a01; op[64] = a02;
    op += NCOL; op[0] = a10; op[32] = a11; op[64] = a12;
    op += NCOL; op[0] = a20; op[32] = a21; op[64] = a22;
    op += NCOL; op[0] = a30; op[32] = a31; op[64] = a32;
}

// ---------------------------------------------------------------------------
// Kernel 3: warp-per-proposal reduce + softmax + decode. grid(128), b(128).
// ---------------------------------------------------------------------------
__global__ void reduce_kernel(const float* __restrict__ prop,
                              const float* __restrict__ bc,
                              const float* __restrict__ bb,
                              float* __restrict__ boxes,
                              float* __restrict__ scores) {
    int wid = threadIdx.x >> 5;
    int lane = threadIdx.x & 31;
    int gid = blockIdx.x * 4 + wid;

    float v0 = 0.f, v1 = 0.f, v2 = 0.f;
    #pragma unroll
    for (int ks = 0; ks < KSPLIT; ks++) {
        const float* q = g_part + (size_t)ks * NPROP * NCOL + (size_t)gid * NCOL;
        v0 += q[lane];
        v1 += q[lane + 32];
        v2 += q[lane + 64];
    }
    int c2 = lane + 64;
    v0 += bc[lane];
    v1 += bc[lane + 32];
    if (c2 <= NUM_CLASSES) v2 += bc[c2];
    else if (c2 <= NUM_CLASSES + 4) v2 += bb[c2 - 81];

    float m = fmaxf(fmaxf(v0, v1), (c2 <= NUM_CLASSES) ? v2 : -INFINITY);
    #pragma unroll
    for (int o = 16; o; o >>= 1) m = fmaxf(m, __shfl_xor_sync(0xffffffffu, m, o));

    float e0 = expf(v0 - m);
    float e1 = expf(v1 - m);
    float e2 = (c2 <= NUM_CLASSES) ? expf(v2 - m) : 0.0f;
    float ssum = e0 + e1 + e2;
    #pragma unroll
    for (int o = 16; o; o >>= 1) ssum += __shfl_xor_sync(0xffffffffu, ssum, o);

    float fg = fmaxf(e0, e1);
    if (c2 < NUM_CLASSES) fg = fmaxf(fg, e2);
    #pragma unroll
    for (int o = 16; o; o >>= 1) fg = fmaxf(fg, __shfl_xor_sync(0xffffffffu, fg, o));

    float dx = __shfl_sync(0xffffffffu, v2, 17);   // col 81
    float dy = __shfl_sync(0xffffffffu, v2, 18);   // col 82
    float dwv = __shfl_sync(0xffffffffu, v2, 19);  // col 83
    float dhv = __shfl_sync(0xffffffffu, v2, 20);  // col 84

    if (lane == 0) {
        scores[gid] = fg / ssum;

        const float* p = prop + (size_t)gid * 4;
        float px1 = p[0], py1 = p[1], px2 = p[2], py2 = p[3];
        float wdt = px2 - px1, hgt = py2 - py1;
        float cx = px1 + 0.5f * wdt, cy = py1 + 0.5f * hgt;
        float ddx = dx * 0.1f;
        float ddy = dy * 0.1f;
        float ddw = fminf(dwv * 0.2f, SCALE_CLAMP);
        float ddh = fminf(dhv * 0.2f, SCALE_CLAMP);
        float pcx = ddx * wdt + cx;
        float pcy = ddy * hgt + cy;
        float pw = expf(ddw) * wdt;
        float ph = expf(ddh) * hgt;
        float* ob = boxes + (size_t)gid * 4;
        ob[0] = fminf(fmaxf(pcx - 0.5f * pw, 0.0f), IMG_W);
        ob[1] = fminf(fmaxf(pcy - 0.5f * ph, 0.0f), IMG_H);
        ob[2] = fminf(fmaxf(pcx + 0.5f * pw, 0.0f), IMG_W);
        ob[3] = fminf(fmaxf(pcy + 0.5f * ph, 0.0f), IMG_H);
    }
}

// ---------------------------------------------------------------------------
// Kernel 4: warp-per-proposal stable descending rank + sorted-box scatter.
// grid(32, 2), block(256) = 8 warps = 8 proposals.
// ---------------------------------------------------------------------------
__global__ void sort_kernel(const float* __restrict__ boxes,
                            const float* __restrict__ scores) {
    int n = blockIdx.y;
    int i = blockIdx.x * 8 + (threadIdx.x >> 5);
    int lane = threadIdx.x & 31;
    int gid = n * NR + i;

    float s_i = scores[gid];
    int cnt = 0;
    #pragma unroll
    for (int jj = 0; jj < 8; jj++) {
        int j = lane + jj * 32;
        float sj = scores[n * NR + j];
        cnt += (sj > s_i) || (sj == s_i && j < i);
    }
    #pragma unroll
    for (int o = 16; o; o >>= 1) cnt += __shfl_xor_sync(0xffffffffu, cnt, o);

    if (lane == 0) {
        g_rank[gid] = cnt;
        ((float4*)g_sboxes)[n * NR + cnt] = ((const float4*)boxes)[gid];
    }
}

// ---------------------------------------------------------------------------
// Kernel 5: IoU suppression bitmatrix. grid(8, 2), block(256).
// ---------------------------------------------------------------------------
__global__ void iou_kernel() {
    __shared__ float4 sb[NR];
    int n = blockIdx.y;
    int t = threadIdx.x;

    for (int i = t; i < NR; i += 256) sb[i] = ((const float4*)g_sboxes)[n * NR + i];
    __syncthreads();

    int r = blockIdx.x * 32 + (t >> 3);
    int w = t & 7;

    float4 a = sb[r];
    float aa = (a.z - a.x) * (a.w - a.y);
    unsigned int word = 0;
    #pragma unroll 8
    for (int k = 0; k < 32; k++) {
        float4 b = sb[w * 32 + k];
        float ba = (b.z - b.x) * (b.w - b.y);
        float lx = fmaxf(a.x, b.x), ly = fmaxf(a.y, b.y);
        float rx = fminf(a.z, b.z), ry = fminf(a.w, b.w);
        float ww = fmaxf(rx - lx, 0.0f), hh = fmaxf(ry - ly, 0.0f);
        float inter = ww * hh;
        float u = fmaxf(aa + ba - inter, 1e-9f);
        if (inter > NMS_TH * u) word |= (1u << k);
    }
    g_supmask[(n * NR + r) * 8 + w] = word;
}

// ---------------------------------------------------------------------------
// Kernel 6: fused greedy + score threshold + stable rank<100 + det write.
// grid(2), block(256). Warp 0 runs the register/ballot greedy, then every
// thread computes its proposal's final keep via the smem smask rank loop
// (identical ops to the R11 finish_kernel).
// ---------------------------------------------------------------------------
__global__ void finish_kernel(const float* __restrict__ boxes,
                              const float* __restrict__ scores,
                              float* __restrict__ det) {
    int n = blockIdx.x;
    int t = threadIdx.x;
    int gid = n * NR + t;

    __shared__ unsigned int keptw[8];
    __shared__ float smask[NR];

    if (t < 32) {
        unsigned kept[8];
        #pragma unroll
        for (int w = 0; w < 8; w++) kept[w] = 0u;
        #pragma unroll
        for (int w = 0; w < 8; w++) {
            int i = w * 32 + t;
            uint4 q0 = *(const uint4*)&g_supmask[(n * NR + i) * 8];
            uint4 q1 = *(const uint4*)&g_supmask[(n * NR + i) * 8 + 4];
            unsigned rw[8] = {q0.x, q0.y, q0.z, q0.w, q1.x, q1.y, q1.z, q1.w};
            unsigned m = 0;
            #pragma unroll
            for (int w2 = 0; w2 < 8; w2++)
                if (w2 < w) m |= rw[w2] & kept[w2];
            bool sup_prev = (m != 0u);
            unsigned myw = rw[w];
            unsigned kw = 0u;
            #pragma unroll
            for (int k = 0; k < 32; k++) {
                bool keep_me = (!sup_prev) && ((myw & kw) == 0u);
                unsigned b = __ballot_sync(0xffffffffu, keep_me);
                kw |= (b & (1u << k));
            }
            kept[w] = kw;
        }
        #pragma unroll
        for (int w = 0; w < 8; w++)
            if (t == w) keptw[w] = kept[w];
    }

    float s_i = scores[gid];
    int rk = g_rank[gid];
    __syncthreads();

    bool kp = (keptw[rk >> 5] >> (rk & 31)) & 1u;
    kp = kp && (s_i > SCORE_TH);
    smask[t] = kp ? s_i : -INFINITY;
    __syncthreads();

    int rank2 = 0;
    float mi = smask[t];
    #pragma unroll 8
    for (int j = 0; j < NR; j++) {
        float mj = smask[j];
        rank2 += (mj > mi) || (mj == mi && j < t);
    }
    kp = kp && (rank2 < MAX_DET);

    const float* bsrc = boxes + (size_t)gid * 4;
    float* drow = det + (size_t)gid * 6;
    drow[0] = bsrc[0]; drow[1] = bsrc[1];
    drow[2] = bsrc[2]; drow[3] = bsrc[3];
    drow[4] = s_i;
    drow[5] = kp ? 1.0f : 0.0f;
}

// ---------------------------------------------------------------------------
extern "C" void kernel_launch(void* const* d_in, const int* in_sizes, int n_in,
                              void* d_out, int out_size) {
    const float* features = (const float*)d_in[0];
    const float* proposals = (const float*)d_in[1];
    const float* gt_boxes = (const float*)d_in[2];
    // d_in[3] = gt_classes (unused by reference)
    const float* W_cls = (const float*)d_in[4];
    const float* b_cls = (const float*)d_in[5];
    const float* W_box = (const float*)d_in[6];
    const float* b_box = (const float*)d_in[7];

    float* out = (float*)d_out;
    float* det = out;                          // 2*256*6 = 3072
    float* out_idx = out + NIMG * NR * 6;      // 512
    float* out_lbl = out_idx + NIMG * NR;      // 512

    float* featvec; cudaGetSymbolAddress((void**)&featvec, g_featvec);
    float* boxes;   cudaGetSymbolAddress((void**)&boxes, g_boxes);
    float* scores;  cudaGetSymbolAddress((void**)&scores, g_scores);

    const int GEMM_SMEM = (MTILE * KSLICE + KSLICE * NCOL) * 4;    // 65536 B
    cudaFuncSetAttribute(gemm_kernel,
                         cudaFuncAttributeMaxDynamicSharedMemorySize, GEMM_SMEM);

    roi_kernel<<<dim3(NR, NIMG), 256>>>(features, proposals, gt_boxes,
                                        featvec, out_idx, out_lbl);
    gemm_kernel<<<dim3(NPROP / MTILE, KSPLIT), 256, GEMM_SMEM>>>(featvec,
                                                                 W_cls, W_box);
    reduce_kernel<<<NPROP / 4, 128>>>(proposals, b_cls, b_box, boxes, scores);
    sort_kernel<<<dim3(NR / 8, NIMG), 256>>>(boxes, scores);
    iou_kernel<<<dim3(8, NIMG), 256>>>();
    finish_kernel<<<NIMG, NR>>>(boxes, scores, det);
}